// round 15
// baseline (speedup 1.0000x reference)
#include <cuda_runtime.h>
#include <cuda_fp16.h>
#include <cstdint>
#include <cstddef>

// ---------------------------------------------------------------------------
// GatedGraphConv (10 layers) + GRUCell.
//  - Algebra: segment_sum linear => gi = aggH @ (w_ih@W_l^T)^T + b_ih
//  - fp16 2-term split: A = Ah + Al (fp16), weights single fp16.
//  - h and agg stored PRE-SPLIT as [row][128 hi | 128 lo] fp16 pairs, so the
//    fused kernel's A/B tiles are pure cp.async copies (no convert on the
//    occ-1 critical path). Split work lives in the latency-bound gather
//    kernel and the GRU epilogue.
// ---------------------------------------------------------------------------

#define C_DIM 128
#define N_MAX 100352
#define E_MAX 1048576
#define L_MAX 16
#define WCAT_PER_L 98304   // 2*128*256 (r,z concat) + 128*128 (in) + 128*128 (hn)

__device__ __align__(128) __half g_h2  [(size_t)N_MAX * 256];   // [hi(128)|lo(128)]
__device__ __align__(128) __half g_agg2[(size_t)N_MAX * 256];
__device__ __align__(128) float  g_bl  [(size_t)L_MAX * 3 * C_DIM * C_DIM];
__device__ __align__(128) __half g_wcat[(size_t)L_MAX * WCAT_PER_L];
__device__ __align__(128) int g_src[E_MAX];
__device__ __align__(128) int g_dst[E_MAX];
__device__ __align__(128) int g_sorted_src[E_MAX];
__device__ __align__(128) int g_deg    [N_MAX];
__device__ __align__(128) int g_partial[N_MAX];
__device__ __align__(128) int g_rowptr [N_MAX + 1];
__device__ __align__(128) int g_cursor [N_MAX];
__device__ __align__(128) int g_bsums  [256];
__device__ int g_is64;

// ============================ helpers ======================================
__device__ __forceinline__ uint32_t smem_u32(const void* p) {
    uint32_t a;
    asm("{ .reg .u64 t; cvta.to.shared.u64 t, %1; cvt.u32.u64 %0, t; }" : "=r"(a) : "l"(p));
    return a;
}
__device__ __forceinline__ void ldmatrix_x4(uint32_t& r0, uint32_t& r1,
                                            uint32_t& r2, uint32_t& r3, uint32_t addr) {
    asm volatile("ldmatrix.sync.aligned.m8n8.x4.shared.b16 {%0,%1,%2,%3}, [%4];"
                 : "=r"(r0), "=r"(r1), "=r"(r2), "=r"(r3) : "r"(addr));
}
__device__ __forceinline__ void mma_fp16(float* d, const uint32_t* a, const uint32_t* b) {
    asm volatile(
        "mma.sync.aligned.m16n8k16.row.col.f32.f16.f16.f32 "
        "{%0,%1,%2,%3}, {%4,%5,%6,%7}, {%8,%9}, {%0,%1,%2,%3};"
        : "+f"(d[0]), "+f"(d[1]), "+f"(d[2]), "+f"(d[3])
        : "r"(a[0]), "r"(a[1]), "r"(a[2]), "r"(a[3]), "r"(b[0]), "r"(b[1]));
}
__device__ __forceinline__ void cp_async16(uint32_t dst, const void* src) {
    asm volatile("cp.async.cg.shared.global [%0], [%1], 16;" :: "r"(dst), "l"(src));
}
#define CP_COMMIT() asm volatile("cp.async.commit_group;" ::: "memory")
#define CP_WAIT(n)  asm volatile("cp.async.wait_group %0;" :: "n"(n) : "memory")

__device__ __forceinline__ float sigmoidf_(float x) { return 1.f / (1.f + __expf(-x)); }

// split float4 -> packed fp16 hi x4 and fp16 lo x4
__device__ __forceinline__ void split4h(float4 v, uint2& hi, uint2& lo) {
    __half hx = __float2half_rn(v.x), hy = __float2half_rn(v.y);
    __half hz = __float2half_rn(v.z), hw = __float2half_rn(v.w);
    __half ox = __float2half_rn(v.x - __half2float(hx));
    __half oy = __float2half_rn(v.y - __half2float(hy));
    __half oz = __float2half_rn(v.z - __half2float(hz));
    __half ow = __float2half_rn(v.w - __half2float(hw));
    hi.x = (uint32_t)__half_as_ushort(hx) | ((uint32_t)__half_as_ushort(hy) << 16);
    hi.y = (uint32_t)__half_as_ushort(hz) | ((uint32_t)__half_as_ushort(hw) << 16);
    lo.x = (uint32_t)__half_as_ushort(ox) | ((uint32_t)__half_as_ushort(oy) << 16);
    lo.y = (uint32_t)__half_as_ushort(oz) | ((uint32_t)__half_as_ushort(ow) << 16);
}
// reconstruct 4 floats from packed hi/lo
__device__ __forceinline__ float4 rec4(uint2 hi, uint2 lo) {
    __half2 h0 = *reinterpret_cast<__half2*>(&hi.x);
    __half2 h1 = *reinterpret_cast<__half2*>(&hi.y);
    __half2 l0 = *reinterpret_cast<__half2*>(&lo.x);
    __half2 l1 = *reinterpret_cast<__half2*>(&lo.y);
    float4 r;
    r.x = __half2float(h0.x) + __half2float(l0.x);
    r.y = __half2float(h0.y) + __half2float(l0.y);
    r.z = __half2float(h1.x) + __half2float(l1.x);
    r.w = __half2float(h1.y) + __half2float(l1.y);
    return r;
}
__device__ __forceinline__ uint32_t packh(float a, float b) {
    __half ha = __float2half_rn(a), hb = __float2half_rn(b);
    return (uint32_t)__half_as_ushort(ha) | ((uint32_t)__half_as_ushort(hb) << 16);
}

// ============================ prologue kernels =============================
__global__ void detect_edge_dtype_kernel(const int* __restrict__ e32, int nscan) {
    if (threadIdx.x == 0 && blockIdx.x == 0) {
        int acc = 0;
        for (int i = 1; i < nscan; i += 2) acc |= e32[i];
        g_is64 = (acc == 0) ? 1 : 0;
    }
}
__global__ void decode_edges_kernel(const int* __restrict__ e32, int E) {
    int i = blockIdx.x * blockDim.x + threadIdx.x;
    if (i >= E) return;
    if (g_is64) { g_src[i] = e32[2 * (size_t)i]; g_dst[i] = e32[2 * ((size_t)E + i)]; }
    else        { g_src[i] = e32[i];             g_dst[i] = e32[(size_t)E + i]; }
}
// h2 = split(x)
__global__ void split_x_kernel(const float4* __restrict__ x, __half* __restrict__ h2, int n4) {
    int i = blockIdx.x * blockDim.x + threadIdx.x;
    if (i >= n4) return;
    int row = i >> 5, c4 = i & 31;
    uint2 hi, lo;
    split4h(x[i], hi, lo);
    *reinterpret_cast<uint2*>(h2 + (size_t)row * 256 + c4 * 4)       = hi;
    *reinterpret_cast<uint2*>(h2 + (size_t)row * 256 + 128 + c4 * 4) = lo;
}

// wcat per layer: [0,65536): g in {r,z}: [c][k] k<128 -> Bl[g*128+c][k] else whh
//                 [65536,81920): in rows ; [81920,98304): hn rows
__global__ void build_wcat_kernel(const float* __restrict__ bl,
                                  const float* __restrict__ whh, int total) {
    int i = blockIdx.x * blockDim.x + threadIdx.x;
    if (i >= total) return;
    int l = i / WCAT_PER_L;
    int r = i - l * WCAT_PER_L;
    float v;
    if (r < 65536) {
        int g = r >> 15, rem = r & 32767, c = rem >> 8, k = rem & 255;
        int row = g * 128 + c;
        v = (k < 128) ? bl[(size_t)l * 49152 + row * 128 + k]
                      : whh[row * 128 + (k - 128)];
    } else {
        int r2 = r - 65536;
        int m = r2 >> 14, rem = r2 & 16383, c = rem >> 7, k = rem & 127;
        int row = 256 + c;
        v = m ? whh[row * 128 + k] : bl[(size_t)l * 49152 + row * 128 + k];
    }
    g_wcat[i] = __float2half_rn(v);
}

// ---- CSR build (once per call) ----
__global__ void zero_int_kernel(int* __restrict__ p, int n) {
    int i = blockIdx.x * blockDim.x + threadIdx.x;
    if (i < n) p[i] = 0;
}
__global__ void hist_kernel(int E) {
    int i = blockIdx.x * blockDim.x + threadIdx.x;
    if (i < E) atomicAdd(&g_deg[g_dst[i]], 1);
}
#define SCAN_BLK 1024
__global__ void scan_block_kernel(int N) {
    __shared__ int sh[SCAN_BLK];
    int tid = threadIdx.x;
    int gid = blockIdx.x * SCAN_BLK + tid;
    int v = (gid < N) ? g_deg[gid] : 0;
    sh[tid] = v; __syncthreads();
    for (int off = 1; off < SCAN_BLK; off <<= 1) {
        int t = (tid >= off) ? sh[tid - off] : 0;
        __syncthreads();
        sh[tid] += t;
        __syncthreads();
    }
    if (gid < N) g_partial[gid] = sh[tid] - v;
    if (tid == SCAN_BLK - 1) g_bsums[blockIdx.x] = sh[tid];
}
__global__ void scan_sums_kernel(int nb) {
    if (threadIdx.x == 0 && blockIdx.x == 0) {
        int run = 0;
        for (int i = 0; i < nb; i++) { int t = g_bsums[i]; g_bsums[i] = run; run += t; }
    }
}
__global__ void scan_add_kernel(int N, int E) {
    int gid = blockIdx.x * blockDim.x + threadIdx.x;
    if (gid < N) {
        int v = g_partial[gid] + g_bsums[gid / SCAN_BLK];
        g_rowptr[gid] = v;
        g_cursor[gid] = v;
    }
    if (gid == N) g_rowptr[N] = E;
}
__global__ void csr_fill_kernel(int E) {
    int i = blockIdx.x * blockDim.x + threadIdx.x;
    if (i >= E) return;
    int pos = atomicAdd(&g_cursor[g_dst[i]], 1);
    g_sorted_src[pos] = g_src[i];
}

// ---- per-layer aggregation: warp per node, 2-way unrolled; reads h2 pairs,
// accumulates fp32, writes agg2 pre-split ----
__global__ void aggregate_csr_kernel(const __half* __restrict__ h2,
                                     __half* __restrict__ agg2, int N)
{
    int t = blockIdx.x * blockDim.x + threadIdx.x;
    int node = t >> 5, lane = t & 31;
    if (node >= N) return;
    int e0 = g_rowptr[node], e1 = g_rowptr[node + 1];
    float4 acc0 = make_float4(0.f, 0.f, 0.f, 0.f);
    float4 acc1 = make_float4(0.f, 0.f, 0.f, 0.f);
    int e = e0;
    for (; e + 2 <= e1; e += 2) {
        int s0 = g_sorted_src[e];
        int s1 = g_sorted_src[e + 1];
        const uint2* r0 = reinterpret_cast<const uint2*>(h2 + (size_t)s0 * 256);
        const uint2* r1 = reinterpret_cast<const uint2*>(h2 + (size_t)s1 * 256);
        uint2 h0 = __ldg(r0 + lane), l0 = __ldg(r0 + 32 + lane);
        uint2 h1 = __ldg(r1 + lane), l1 = __ldg(r1 + 32 + lane);
        float4 v0 = rec4(h0, l0);
        float4 v1 = rec4(h1, l1);
        acc0.x += v0.x; acc0.y += v0.y; acc0.z += v0.z; acc0.w += v0.w;
        acc1.x += v1.x; acc1.y += v1.y; acc1.z += v1.z; acc1.w += v1.w;
    }
    if (e < e1) {
        int s0 = g_sorted_src[e];
        const uint2* r0 = reinterpret_cast<const uint2*>(h2 + (size_t)s0 * 256);
        uint2 h0 = __ldg(r0 + lane), l0 = __ldg(r0 + 32 + lane);
        float4 v0 = rec4(h0, l0);
        acc0.x += v0.x; acc0.y += v0.y; acc0.z += v0.z; acc0.w += v0.w;
    }
    acc0.x += acc1.x; acc0.y += acc1.y; acc0.z += acc1.z; acc0.w += acc1.w;
    uint2 hi, lo;
    split4h(acc0, hi, lo);
    *reinterpret_cast<uint2*>(agg2 + (size_t)node * 256 + lane * 4)       = hi;
    *reinterpret_cast<uint2*>(agg2 + (size_t)node * 256 + 128 + lane * 4) = lo;
}

// ================= SIMT NT GEMM (tiny B_l precompute, batched over z) ======
__global__ void __launch_bounds__(256) gemm_nt_batched_kernel(
    const float* __restrict__ A, const float* __restrict__ Wall,
    float* __restrict__ CoutAll, int M, int nout)
{
    __shared__ float As[64][68];
    __shared__ float Bs[64][68];
    const float* B = Wall + (size_t)blockIdx.z * C_DIM * C_DIM;
    float* Cout = CoutAll + (size_t)blockIdx.z * 3 * C_DIM * C_DIM;
    const int tid = threadIdx.x;
    const int row0 = blockIdx.x * 64, col0 = blockIdx.y * 64;
    const int tx = tid & 15, ty = tid >> 4;
    float acc[4][4];
#pragma unroll
    for (int i = 0; i < 4; i++)
#pragma unroll
        for (int j = 0; j < 4; j++) acc[i][j] = 0.f;
#pragma unroll
    for (int kt = 0; kt < 2; kt++) {
#pragma unroll
        for (int s = 0; s < 4; s++) {
            int i = tid + s * 256, r = i >> 4, c4 = i & 15;
            float4 va = make_float4(0.f, 0.f, 0.f, 0.f);
            if (row0 + r < M)
                va = *reinterpret_cast<const float4*>(A + (size_t)(row0 + r) * C_DIM + kt * 64 + c4 * 4);
            *reinterpret_cast<float4*>(&As[r][c4 * 4]) = va;
            float4 vb = *reinterpret_cast<const float4*>(B + (size_t)(col0 + r) * C_DIM + kt * 64 + c4 * 4);
            *reinterpret_cast<float4*>(&Bs[r][c4 * 4]) = vb;
        }
        __syncthreads();
#pragma unroll
        for (int k4 = 0; k4 < 16; k4++) {
            float4 a[4], b[4];
#pragma unroll
            for (int i = 0; i < 4; i++) a[i] = *reinterpret_cast<const float4*>(&As[ty * 4 + i][k4 * 4]);
#pragma unroll
            for (int j = 0; j < 4; j++) b[j] = *reinterpret_cast<const float4*>(&Bs[tx * 4 + j][k4 * 4]);
#pragma unroll
            for (int i = 0; i < 4; i++)
#pragma unroll
                for (int j = 0; j < 4; j++) {
                    acc[i][j] += a[i].x * b[j].x; acc[i][j] += a[i].y * b[j].y;
                    acc[i][j] += a[i].z * b[j].z; acc[i][j] += a[i].w * b[j].w;
                }
        }
        __syncthreads();
    }
#pragma unroll
    for (int i = 0; i < 4; i++) {
        int r = row0 + ty * 4 + i;
        if (r < M)
#pragma unroll
            for (int j = 0; j < 4; j++)
                Cout[(size_t)r * nout + col0 + tx * 4 + j] = acc[i][j];
    }
}

// ================== fused layer kernel (GEMMs + GRU) =======================
// CTA: 64 rows. A tile = [agg | h] 64 x 256 fp16, hi + lo -- pure cp.async
// from pre-split agg2/h2. B: two cp.async ping-pong buffers. Phases:
//   r (K=256, buf0) -> z (K=256, buf1) -> n (in+hn K=128 pair, buf0).
#define A_LDA 528                       // 256 fp16 * 2 + 16B pad
#define A_TILE (64 * A_LDA)             // 33792
#define B_LDA_RZ 528
#define B_LDA_N  272
#define B_BUF 69632                     // fits rz (128*528=67584) or n pair (2*34816)
#define SM_AHI 0
#define SM_ALO A_TILE
#define SM_B0  (2 * A_TILE)             // 67584
#define SM_B1  (2 * A_TILE + B_BUF)     // 137216
#define SM_TOT (2 * A_TILE + 2 * B_BUF) // 206848

__device__ __forceinline__ void load_b_rz_async(uint32_t dstbase,
    const __half* __restrict__ wsrc, int tid)
{
#pragma unroll
    for (int it = 0; it < 8; it++) {
        int idx = tid + it * 512;       // 0..4095
        int r = idx >> 5, c = idx & 31;
        cp_async16(dstbase + (uint32_t)r * B_LDA_RZ + c * 16,
                   wsrc + (size_t)r * 256 + c * 8);
    }
}
__device__ __forceinline__ void load_b_n_async(uint32_t dstbase,
    const __half* __restrict__ wsrc, int tid)
{
#pragma unroll
    for (int it = 0; it < 8; it++) {
        int idx = tid + it * 512;       // 0..4095
        int m = idx >> 11, rem = idx & 2047;
        int r = rem >> 4, c = rem & 15;
        cp_async16(dstbase + m * 34816 + (uint32_t)r * B_LDA_N + c * 16,
                   wsrc + m * 16384 + (size_t)r * 128 + c * 8);
    }
}

// One GEMM phase: acc[2][2][4] += (Ah + Al) @ B over ksteps.
__device__ __forceinline__ void phase2(uint32_t aH0, uint32_t aL0, uint32_t bB0,
                                       const int ksteps, float acc[2][2][4])
{
#pragma unroll
    for (int ks = 0; ks < ksteps; ks++) {
        const uint32_t koff = ks * 32;
        uint32_t aH[2][4], aL[2][4], bH[4];
#pragma unroll
        for (int im = 0; im < 2; im++) {
            ldmatrix_x4(aH[im][0], aH[im][1], aH[im][2], aH[im][3],
                        aH0 + (uint32_t)im * 16 * A_LDA + koff);
            ldmatrix_x4(aL[im][0], aL[im][1], aL[im][2], aL[im][3],
                        aL0 + (uint32_t)im * 16 * A_LDA + koff);
        }
        ldmatrix_x4(bH[0], bH[1], bH[2], bH[3], bB0 + koff);
#pragma unroll
        for (int im = 0; im < 2; im++)
#pragma unroll
            for (int in = 0; in < 2; in++) {
                mma_fp16(acc[im][in], aH[im], &bH[in * 2]);
                mma_fp16(acc[im][in], aL[im], &bH[in * 2]);
            }
    }
}

__global__ void __launch_bounds__(512, 1)
fused_layer_kernel(const __half* __restrict__ agg2, __half* __restrict__ h2,
                   const __half* __restrict__ wl,
                   const float* __restrict__ b_ih, const float* __restrict__ b_hh,
                   float* __restrict__ out_relu, int M)
{
    extern __shared__ char smem[];
    const uint32_t sb = smem_u32(smem);
    const int tid  = threadIdx.x;
    const int wid  = tid >> 5;
    const int lane = tid & 31;
    const int row0 = blockIdx.x * 64;
    const int wm = wid & 1;        // 2 row groups of 32
    const int wn = wid >> 1;       // 8 col groups of 16 (over 384 gate cols)

    // ---- group 0: A tile (pre-split, pure copies) ----
    // hi buffer rows: [agg_hi | h_hi]; lo buffer rows: [agg_lo | h_lo]
#pragma unroll
    for (int it = 0; it < 8; it++) {
        int idx = tid + it * 512;          // 0..4095
        int sel = idx >> 11;               // 0 = hi, 1 = lo
        int rem = idx & 2047;
        int row = rem >> 5;                // 0..63
        int c   = rem & 31;                // 16B chunk within 512B row
        const __half* srcb = (c < 16) ? agg2 : h2;
        int cc = c & 15;
        const __half* src = srcb + (size_t)(row0 + row) * 256 + sel * 128 + cc * 8;
        uint32_t dst = sb + (sel ? SM_ALO : SM_AHI) + (uint32_t)row * A_LDA + c * 16;
        cp_async16(dst, src);
    }
    CP_COMMIT();                                        // group: A
    load_b_rz_async(sb + SM_B0, wl, tid);               // rz gate 0 (r)
    CP_COMMIT();                                        // group: B0
    load_b_rz_async(sb + SM_B1, wl + 32768, tid);       // rz gate 1 (z)
    CP_COMMIT();                                        // group: B1

    // ---- fragment addressing ----
    const uint32_t a_off =
        (uint32_t)(wm * 32 + (lane & 15)) * A_LDA + (uint32_t)(lane >> 4) * 16;
    const uint32_t aH0 = sb + SM_AHI + a_off;
    const uint32_t aL0 = sb + SM_ALO + a_off;
    const uint32_t b_row = (uint32_t)(wn * 16 + ((lane >> 4) & 1) * 8 + (lane & 7));
    const uint32_t b_col = (uint32_t)((lane >> 3) & 1) * 16;
    const uint32_t bRZ0 = sb + SM_B0 + b_row * B_LDA_RZ + b_col;
    const uint32_t bRZ1 = sb + SM_B1 + b_row * B_LDA_RZ + b_col;
    const uint32_t bN0  = sb + SM_B0 + b_row * B_LDA_N  + b_col;

    float acc_r [2][2][4], acc_z [2][2][4], acc_in[2][2][4], acc_hn[2][2][4];
#pragma unroll
    for (int im = 0; im < 2; im++)
#pragma unroll
        for (int in = 0; in < 2; in++)
#pragma unroll
            for (int q = 0; q < 4; q++) {
                acc_r[im][in][q] = 0.f; acc_z[im][in][q] = 0.f;
                acc_in[im][in][q] = 0.f; acc_hn[im][in][q] = 0.f;
            }

    // ---- phase r: A(K=256) x buf0 ----
    CP_WAIT(1);            // A + B0 complete (B1 may be in flight)
    __syncthreads();
    phase2(aH0, aL0, bRZ0, 16, acc_r);
    __syncthreads();       // all warps done with buf0
    load_b_n_async(sb + SM_B0, wl + 65536, tid);        // n pair -> buf0
    CP_COMMIT();                                        // group: Bn

    // ---- phase z: A(K=256) x buf1 ----
    CP_WAIT(1);            // B1 complete (Bn may be in flight)
    __syncthreads();
    phase2(aH0, aL0, bRZ1, 16, acc_z);

    // ---- phase n: in (agg half) + hn (h half), K=128 each, buf0 ----
    CP_WAIT(0);
    __syncthreads();
    phase2(aH0,       aL0,       bN0,         8, acc_in);   // K cols 0-127 (agg)
    phase2(aH0 + 256, aL0 + 256, bN0 + 34816, 8, acc_hn);   // K cols 128-255 (h)

    // ---- epilogue: GRU, h2 in-place update ----
    const int row_l = lane >> 2;
    const int col_l = (lane & 3) * 2;
#pragma unroll
    for (int in = 0; in < 2; in++) {
        const int c = wn * 16 + in * 8 + col_l;
        const float bir0 = __ldg(b_ih + c),       bir1 = __ldg(b_ih + c + 1);
        const float bhr0 = __ldg(b_hh + c),       bhr1 = __ldg(b_hh + c + 1);
        const float biz0 = __ldg(b_ih + 128 + c), biz1 = __ldg(b_ih + 129 + c);
        const float bhz0 = __ldg(b_hh + 128 + c), bhz1 = __ldg(b_hh + 129 + c);
        const float bin0 = __ldg(b_ih + 256 + c), bin1 = __ldg(b_ih + 257 + c);
        const float bhn0 = __ldg(b_hh + 256 + c), bhn1 = __ldg(b_hh + 257 + c);
#pragma unroll
        for (int im = 0; im < 2; im++) {
#pragma unroll
            for (int q = 0; q < 2; q++) {
                int r = row0 + wm * 32 + im * 16 + q * 8 + row_l;
                if (r >= M) continue;
                __half* h2row = h2 + (size_t)r * 256;
                uint32_t hu = *reinterpret_cast<const uint32_t*>(h2row + c);
                uint32_t lu = *reinterpret_cast<const uint32_t*>(h2row + 128 + c);
                __half2 hh = *reinterpret_cast<__half2*>(&hu);
                __half2 ll = *reinterpret_cast<__half2*>(&lu);
                float hold0 = __half2float(hh.x) + __half2float(ll.x);
                float hold1 = __half2float(hh.y) + __half2float(ll.y);

                float rr0 = sigmoidf_(acc_r[im][in][q * 2 + 0] + bir0 + bhr0);
                float rr1 = sigmoidf_(acc_r[im][in][q * 2 + 1] + bir1 + bhr1);
                float zz0 = sigmoidf_(acc_z[im][in][q * 2 + 0] + biz0 + bhz0);
                float zz1 = sigmoidf_(acc_z[im][in][q * 2 + 1] + biz1 + bhz1);
                float nn0 = tanhf(acc_in[im][in][q * 2 + 0] + bin0 + rr0 * (acc_hn[im][in][q * 2 + 0] + bhn0));
                float nn1 = tanhf(acc_in[im][in][q * 2 + 1] + bin1 + rr1 * (acc_hn[im][in][q * 2 + 1] + bhn1));
                float h0 = (1.f - zz0) * nn0 + zz0 * hold0;
                float h1 = (1.f - zz1) * nn1 + zz1 * hold1;

                float h0h = __half2float(__float2half_rn(h0));
                float h1h = __half2float(__float2half_rn(h1));
                *reinterpret_cast<uint32_t*>(h2row + c)       = packh(h0, h1);
                *reinterpret_cast<uint32_t*>(h2row + 128 + c) = packh(h0 - h0h, h1 - h1h);
                if (out_relu)
                    *reinterpret_cast<float2*>(out_relu + (size_t)r * C_DIM + c) =
                        make_float2(fmaxf(h0, 0.f), fmaxf(h1, 0.f));
            }
        }
    }
}

// ============================ launch =======================================
extern "C" void kernel_launch(void* const* d_in, const int* in_sizes, int n_in,
                              void* d_out, int out_size)
{
    const float* x    = (const float*)d_in[0];
    const int*   e32  = (const int*)  d_in[1];
    const float* w    = (const float*)d_in[2];
    const float* w_ih = (const float*)d_in[3];
    const float* w_hh = (const float*)d_in[4];
    const float* b_ih = (const float*)d_in[5];
    const float* b_hh = (const float*)d_in[6];

    const int N = in_sizes[0] / C_DIM;
    const int E = in_sizes[1] / 2;
    const int L = in_sizes[2] / (C_DIM * C_DIM);

    float *p_bl;
    __half *p_h2, *p_agg2, *p_wcat;
    cudaGetSymbolAddress((void**)&p_h2,   g_h2);
    cudaGetSymbolAddress((void**)&p_agg2, g_agg2);
    cudaGetSymbolAddress((void**)&p_bl,   g_bl);
    cudaGetSymbolAddress((void**)&p_wcat, g_wcat);
    int *p_deg;
    cudaGetSymbolAddress((void**)&p_deg, g_deg);

    cudaFuncSetAttribute(fused_layer_kernel,
                         cudaFuncAttributeMaxDynamicSharedMemorySize, SM_TOT);

    // ---- edges + CSR (once) ----
    int nscan = 1024;
    if (2 * E < nscan) nscan = 2 * E;
    detect_edge_dtype_kernel<<<1, 32>>>(e32, nscan);
    decode_edges_kernel<<<(E + 255) / 256, 256>>>(e32, E);
    zero_int_kernel<<<(N + 255) / 256, 256>>>(p_deg, N);
    hist_kernel<<<(E + 255) / 256, 256>>>(E);
    const int nb = (N + SCAN_BLK - 1) / SCAN_BLK;
    scan_block_kernel<<<nb, SCAN_BLK>>>(N);
    scan_sums_kernel<<<1, 32>>>(nb);
    scan_add_kernel<<<(N + 1 + 255) / 256, 256>>>(N, E);
    csr_fill_kernel<<<(E + 255) / 256, 256>>>(E);

    // ---- h2 = split(x) ----
    const int n4 = N * (C_DIM / 4);
    split_x_kernel<<<(n4 + 255) / 256, 256>>>((const float4*)x, p_h2, n4);

    // ---- B_l = w_ih @ W_l^T, then build fp16 concatenated weights ----
    gemm_nt_batched_kernel<<<dim3(6, 2, L), 256>>>(w_ih, w, p_bl, 384, C_DIM);
    {
        int total = L * WCAT_PER_L;
        build_wcat_kernel<<<(total + 255) / 256, 256>>>(p_bl, w_hh, total);
    }

    const int gx = (N + 63) / 64;
    const int agg_blocks = (N * 32 + 255) / 256;

    for (int l = 0; l < L; l++) {
        aggregate_csr_kernel<<<agg_blocks, 256>>>(p_h2, p_agg2, N);
        float* outp = (l == L - 1) ? (float*)d_out : nullptr;
        fused_layer_kernel<<<gx, 512, SM_TOT>>>(
            p_agg2, p_h2, p_wcat + (size_t)l * WCAT_PER_L,
            b_ih, b_hh, outp, N);
    }
}